// round 13
// baseline (speedup 1.0000x reference)
#include <cuda_runtime.h>
#include <cuda_bf16.h>
#include <math.h>
#include <stdint.h>

// ---------------- problem constants ----------------
#define NB   8
#define NC   256
#define NHW  16384     // 128*128
#define NTOK 131072    // NB*NHW
#define NPERSIST 304   // 2 CTAs/SM x 152 SMs (GB300)

typedef __nv_bfloat16 bf16;

// ---------------- scratch (device globals) ----------------
__device__ bf16  g_cat [(size_t)NB * 768 * NHW];   // [B,3C,HW] bf16 (k-major)
__device__ float g_xm  [(size_t)NTOK * NC];        // residual stream (fp32)
__device__ float g_xtok[(size_t)NTOK * NC];        // x token-major (fp32)
__device__ bf16  g_tok [(size_t)NTOK * NC];        // LN'd tokens bf16
__device__ bf16  g_qkv [(size_t)NTOK * 768];
__device__ bf16  g_att [(size_t)NTOK * NC];
__device__ bf16  g_proj[(size_t)NTOK * NC];        // projection outputs (bf16)
__device__ bf16  g_h1  [(size_t)NTOK * 1024];
__device__ bf16  g_wb  [1245184];                  // all weights converted to bf16

// weight offsets in g_wb (elements)
#define OFF_WF   0
#define OFF_QKVW 196608
#define OFF_QKVG 393216
#define OFF_WOW  589824
#define OFF_WOG  655360
#define OFF_M1   720896
#define OFF_M2   983040

// ---------------- helpers ----------------
__device__ __forceinline__ float gelu_exact(float x) {
    return 0.5f * x * (1.0f + erff(x * 0.70710678118654752f));
}
__device__ __forceinline__ uint32_t f2bf2(float a, float b) {
    __nv_bfloat162 h = __floats2bfloat162_rn(a, b);
    return *reinterpret_cast<uint32_t*>(&h);
}
__device__ __forceinline__ float2 bf2f(uint32_t w) {
    __nv_bfloat162 h = *reinterpret_cast<__nv_bfloat162*>(&w);
    return __bfloat1622float2(h);
}
__device__ __forceinline__ void mma_bf16(float* d, const uint32_t* a, const uint32_t* b) {
    asm volatile(
        "mma.sync.aligned.m16n8k16.row.col.f32.bf16.bf16.f32 "
        "{%0,%1,%2,%3}, {%4,%5,%6,%7}, {%8,%9}, {%0,%1,%2,%3};"
        : "+f"(d[0]), "+f"(d[1]), "+f"(d[2]), "+f"(d[3])
        : "r"(a[0]), "r"(a[1]), "r"(a[2]), "r"(a[3]), "r"(b[0]), "r"(b[1]));
}
__device__ __forceinline__ uint32_t smem_u32(const void* p) {
    return (uint32_t)__cvta_generic_to_shared(p);
}
__device__ __forceinline__ void cp_async16(uint32_t s, const void* gp) {
    asm volatile("cp.async.cg.shared.global [%0], [%1], 16;" :: "r"(s), "l"(gp));
}
__device__ __forceinline__ void cp_commit() {
    asm volatile("cp.async.commit_group;");
}
template<int W> __device__ __forceinline__ void cp_wait() {
    asm volatile("cp.async.wait_group %0;" :: "n"(W));
}
__device__ __forceinline__ void ldsm_x4(uint32_t& a, uint32_t& b, uint32_t& c, uint32_t& d,
                                        uint32_t addr) {
    asm volatile("ldmatrix.sync.aligned.m8n8.x4.shared.b16 {%0,%1,%2,%3}, [%4];"
        : "=r"(a), "=r"(b), "=r"(c), "=r"(d) : "r"(addr));
}
__device__ __forceinline__ void ldsm_x4_t(uint32_t& a, uint32_t& b, uint32_t& c, uint32_t& d,
                                          uint32_t addr) {
    asm volatile("ldmatrix.sync.aligned.m8n8.x4.trans.shared.b16 {%0,%1,%2,%3}, [%4];"
        : "=r"(a), "=r"(b), "=r"(c), "=r"(d) : "r"(addr));
}

// ---------------- merged weight fp32 -> bf16 ----------------
__global__ void cvt_all(const float* __restrict__ wf, const float* __restrict__ qw,
                        const float* __restrict__ qg, const float* __restrict__ ow,
                        const float* __restrict__ og, const float* __restrict__ m1,
                        const float* __restrict__ m2, bf16* __restrict__ d) {
    int i = blockIdx.x * 256 + threadIdx.x;   // quad index
    if (i >= 311296) return;
    const float* src;
    int local;
    if (i < 49152)        { src = wf; local = i; }
    else if (i < 98304)   { src = qw; local = i - 49152; }
    else if (i < 147456)  { src = qg; local = i - 98304; }
    else if (i < 163840)  { src = ow; local = i - 147456; }
    else if (i < 180224)  { src = og; local = i - 163840; }
    else if (i < 245760)  { src = m1; local = i - 180224; }
    else                  { src = m2; local = i - 245760; }
    float4 v = *(const float4*)(src + (size_t)local * 4);
    *(uint2*)(d + (size_t)i * 4) = make_uint2(f2bf2(v.x, v.y), f2bf2(v.z, v.w));
}

// ---------------- 1) fused depthwise convs (3x3,5x5,7x7) -> bf16 cat ----------------
__global__ void dwconv3_kernel(const float* __restrict__ X,
                               const float* __restrict__ w1, const float* __restrict__ b1,
                               const float* __restrict__ w2, const float* __restrict__ b2,
                               const float* __restrict__ w3, const float* __restrict__ b3) {
    __shared__ float sx[38][39];
    __shared__ float swt[83];
    int c = blockIdx.y, b = blockIdx.z;
    int tile = blockIdx.x;
    int ty0 = (tile >> 2) * 32, tx0 = (tile & 3) * 32;
    const float* Xp = X + ((size_t)b * NC + c) * NHW;
    int tid = threadIdx.x;

    if (tid < 9)       swt[tid] = w1[c * 9 + tid];
    else if (tid < 34) swt[tid] = w2[c * 25 + (tid - 9)];
    else if (tid < 83) swt[tid] = w3[c * 49 + (tid - 34)];

    for (int i = tid; i < 38 * 38; i += 256) {
        int iy = i / 38, ix = i - iy * 38;
        int gy = ty0 + iy - 3, gx = tx0 + ix - 3;
        float v = 0.0f;
        if (gy >= 0 && gy < 128 && gx >= 0 && gx < 128) v = Xp[gy * 128 + gx];
        sx[iy][ix] = v;
    }
    __syncthreads();

    float bb1 = b1[c], bb2 = b2[c], bb3 = b3[c];
    size_t ob1 = ((size_t)b * 768 + c) * NHW;
    size_t ob2 = ((size_t)b * 768 + 256 + c) * NHW;
    size_t ob3 = ((size_t)b * 768 + 512 + c) * NHW;

    #pragma unroll
    for (int sub = 0; sub < 4; sub++) {
        int oy = (tid >> 5) + sub * 8;
        int ox = (tid & 31);
        int cy = oy + 3, cx = ox + 3;
        float a1 = bb1, a2 = bb2, a3 = bb3;
        #pragma unroll
        for (int dy = -3; dy <= 3; dy++) {
            #pragma unroll
            for (int dx = -3; dx <= 3; dx++) {
                float v = sx[cy + dy][cx + dx];
                a3 += v * swt[34 + (dy + 3) * 7 + (dx + 3)];
                if (dy >= -2 && dy <= 2 && dx >= -2 && dx <= 2)
                    a2 += v * swt[9 + (dy + 2) * 5 + (dx + 2)];
                if (dy >= -1 && dy <= 1 && dx >= -1 && dx <= 1)
                    a1 += v * swt[(dy + 1) * 3 + (dx + 1)];
            }
        }
        int po = (ty0 + oy) * 128 + tx0 + ox;
        g_cat[ob1 + po] = __float2bfloat16_rn(a1);
        g_cat[ob2 + po] = __float2bfloat16_rn(a2);
        g_cat[ob3 + po] = __float2bfloat16_rn(a3);
    }
}

// ---------------- transpose x [B,C,HW] -> token-major fp32 ----------------
__global__ void to_tok(const float* __restrict__ X, float* __restrict__ T) {
    __shared__ float sm[64][65];
    int p0 = blockIdx.x * 64, c0 = blockIdx.y * 64, b = blockIdx.z;
    int tid = threadIdx.x;
    #pragma unroll
    for (int it = 0; it < 4; it++) {
        int c = it * 16 + (tid >> 4);
        int p4 = (tid & 15) * 4;
        float4 v = *(const float4*)&X[((size_t)(b * NC + c0 + c)) * NHW + p0 + p4];
        sm[c][p4 + 0] = v.x; sm[c][p4 + 1] = v.y; sm[c][p4 + 2] = v.z; sm[c][p4 + 3] = v.w;
    }
    __syncthreads();
    #pragma unroll
    for (int it = 0; it < 4; it++) {
        int p = it * 16 + (tid >> 4);
        int c4 = (tid & 15) * 4;
        float4 v = make_float4(sm[c4][p], sm[c4 + 1][p], sm[c4 + 2][p], sm[c4 + 3][p]);
        *(float4*)&T[((size_t)(b * NHW + p0 + p)) * NC + c0 + c4] = v;
    }
}

// ---------------- final: out[b,c,p] = R[t][c] + P[t][c] (P bf16), transposed ----------------
__global__ void from_tok_add(const float* __restrict__ R, const bf16* __restrict__ P,
                             float* __restrict__ O) {
    __shared__ float sm[64][65];
    int p0 = blockIdx.x * 64, c0 = blockIdx.y * 64, b = blockIdx.z;
    int tid = threadIdx.x;
    #pragma unroll
    for (int it = 0; it < 4; it++) {
        int p = it * 16 + (tid >> 4);
        int c4 = (tid & 15) * 4;
        size_t row = ((size_t)(b * NHW + p0 + p)) * NC + c0 + c4;
        float4 a = *(const float4*)&R[row];
        uint2 qw = *(const uint2*)&P[row];
        float2 qa = bf2f(qw.x), qb = bf2f(qw.y);
        sm[c4 + 0][p] = a.x + qa.x; sm[c4 + 1][p] = a.y + qa.y;
        sm[c4 + 2][p] = a.z + qb.x; sm[c4 + 3][p] = a.w + qb.y;
    }
    __syncthreads();
    #pragma unroll
    for (int it = 0; it < 4; it++) {
        int c = it * 16 + (tid >> 4);
        int p4 = (tid & 15) * 4;
        float4 v = make_float4(sm[c][p4], sm[c][p4 + 1], sm[c][p4 + 2], sm[c][p4 + 3]);
        *(float4*)&O[((size_t)(b * NC + c0 + c)) * NHW + p0 + p4] = v;
    }
}

// ---------------- fused LN + permute -> bf16 tokens (first LN) ----------------
__global__ void ln_perm(const float* __restrict__ R, const float* __restrict__ gam,
                        const float* __restrict__ bet, bf16* __restrict__ T, int mode) {
    int warp = threadIdx.x >> 5, lane = threadIdx.x & 31;
    int t = blockIdx.x * 8 + warp;
    int b = t >> 14, r = t & 16383;
    int p;
    if (mode == 2) p = r;
    else {
        int win = r >> 6, pos = r & 63;
        int wy = win >> 4, wx = win & 15;
        int py = pos >> 3, px = pos & 7;
        if (mode == 0) p = (wy * 8 + py) * 128 + wx * 8 + px;
        else           p = (py * 16 + wy) * 128 + px * 16 + wx;
    }
    const float* src = R + ((size_t)b * NHW + p) * NC;
    float4 v0 = *(const float4*)(src + lane * 4);
    float4 v1 = *(const float4*)(src + 128 + lane * 4);
    float s  = v0.x + v0.y + v0.z + v0.w + v1.x + v1.y + v1.z + v1.w;
    float s2 = v0.x * v0.x + v0.y * v0.y + v0.z * v0.z + v0.w * v0.w
             + v1.x * v1.x + v1.y * v1.y + v1.z * v1.z + v1.w * v1.w;
    #pragma unroll
    for (int o = 16; o; o >>= 1) {
        s  += __shfl_xor_sync(0xffffffff, s, o);
        s2 += __shfl_xor_sync(0xffffffff, s2, o);
    }
    float m = s * (1.0f / NC);
    float rs = rsqrtf(s2 * (1.0f / NC) - m * m + 1e-5f);
    float4 g0 = *(const float4*)(gam + lane * 4);
    float4 g1 = *(const float4*)(gam + 128 + lane * 4);
    float4 b0 = *(const float4*)(bet + lane * 4);
    float4 b1 = *(const float4*)(bet + 128 + lane * 4);
    bf16* dst = T + (size_t)t * NC;
    float o0x = (v0.x - m) * rs * g0.x + b0.x, o0y = (v0.y - m) * rs * g0.y + b0.y;
    float o0z = (v0.z - m) * rs * g0.z + b0.z, o0w = (v0.w - m) * rs * g0.w + b0.w;
    float o1x = (v1.x - m) * rs * g1.x + b1.x, o1y = (v1.y - m) * rs * g1.y + b1.y;
    float o1z = (v1.z - m) * rs * g1.z + b1.z, o1w = (v1.w - m) * rs * g1.w + b1.w;
    *(uint2*)(dst + lane * 4)       = make_uint2(f2bf2(o0x, o0y), f2bf2(o0z, o0w));
    *(uint2*)(dst + 128 + lane * 4) = make_uint2(f2bf2(o1x, o1y), f2bf2(o1z, o1w));
}

// ---------------- fused residual-add (permuted bf16 proj) + LN + permute-out ----------------
__global__ void resadd_ln(const float* __restrict__ base, const bf16* __restrict__ P,
                          float* __restrict__ Rout, const float* __restrict__ gam,
                          const float* __restrict__ bet, bf16* __restrict__ T,
                          int addmode, int lnmode) {
    int warp = threadIdx.x >> 5, lane = threadIdx.x & 31;
    int t = blockIdx.x * 8 + warp;
    int b = t >> 14, p = t & 16383;
    int h = p >> 7, w = p & 127;
    int tp;
    if (addmode == 0) {
        int win = (h >> 3) * 16 + (w >> 3);
        int pos = (h & 7) * 8 + (w & 7);
        tp = (b << 14) + win * 64 + pos;
    } else {
        int K2 = h >> 3, K1 = ((h & 7) << 1) | (w >> 6);
        int S1 = (w >> 3) & 7, S2 = w & 7;
        tp = (b << 14) + (K1 * 16 + K2) * 64 + S1 * 8 + S2;
    }
    const float* pb = base + (size_t)t * NC;
    const bf16* pp = P + (size_t)tp * NC;
    float4 v0 = *(const float4*)(pb + lane * 4);
    float4 v1 = *(const float4*)(pb + 128 + lane * 4);
    uint2 qw0 = *(const uint2*)(pp + lane * 4);
    uint2 qw1 = *(const uint2*)(pp + 128 + lane * 4);
    float2 qa = bf2f(qw0.x), qb = bf2f(qw0.y);
    float2 qc = bf2f(qw1.x), qd = bf2f(qw1.y);
    v0.x += qa.x; v0.y += qa.y; v0.z += qb.x; v0.w += qb.y;
    v1.x += qc.x; v1.y += qc.y; v1.z += qd.x; v1.w += qd.y;
    float* po = Rout + (size_t)t * NC;
    *(float4*)(po + lane * 4) = v0;
    *(float4*)(po + 128 + lane * 4) = v1;

    float s  = v0.x + v0.y + v0.z + v0.w + v1.x + v1.y + v1.z + v1.w;
    float s2 = v0.x * v0.x + v0.y * v0.y + v0.z * v0.z + v0.w * v0.w
             + v1.x * v1.x + v1.y * v1.y + v1.z * v1.z + v1.w * v1.w;
    #pragma unroll
    for (int o = 16; o; o >>= 1) {
        s  += __shfl_xor_sync(0xffffffff, s, o);
        s2 += __shfl_xor_sync(0xffffffff, s2, o);
    }
    float m = s * (1.0f / NC);
    float rs = rsqrtf(s2 * (1.0f / NC) - m * m + 1e-5f);
    float4 g0 = *(const float4*)(gam + lane * 4);
    float4 g1 = *(const float4*)(gam + 128 + lane * 4);
    float4 b0 = *(const float4*)(bet + lane * 4);
    float4 b1 = *(const float4*)(bet + 128 + lane * 4);
    int tout;
    if (lnmode == 2) tout = t;
    else tout = (b << 14) + ((h & 15) * 16 + (w & 15)) * 64 + (h >> 4) * 8 + (w >> 4);
    bf16* dst = T + (size_t)tout * NC;
    float o0x = (v0.x - m) * rs * g0.x + b0.x, o0y = (v0.y - m) * rs * g0.y + b0.y;
    float o0z = (v0.z - m) * rs * g0.z + b0.z, o0w = (v0.w - m) * rs * g0.w + b0.w;
    float o1x = (v1.x - m) * rs * g1.x + b1.x, o1y = (v1.y - m) * rs * g1.y + b1.y;
    float o1z = (v1.z - m) * rs * g1.z + b1.z, o1w = (v1.w - m) * rs * g1.w + b1.w;
    *(uint2*)(dst + lane * 4)       = make_uint2(f2bf2(o0x, o0y), f2bf2(o0z, o0w));
    *(uint2*)(dst + 128 + lane * 4) = make_uint2(f2bf2(o1x, o1y), f2bf2(o1z, o1w));
}

// ================= persistent bf16 NT GEMM: continuous cp.async pipeline =================
// C[M,N] = A[M,K] * B[N,K]^T + bias[n]; 128x128 tiles, BK=64, 8 warps (2x4).
// 304 persistent CTAs; each walks tiles bid, bid+304, ... with ONE pipeline
// across tile boundaries (no per-tile fill/drain). Tile order m-major (A L2 reuse).
#define GSTAGE 32768
#define GEMM_SMEM 98304
template<typename OutT, bool GELU>
__global__ __launch_bounds__(256, 2) void gemm_bf16_nt(
        const bf16* __restrict__ A, const bf16* __restrict__ B,
        const float* __restrict__ bias, OutT* __restrict__ C,
        int N, int K, int numTiles) {
    extern __shared__ uint8_t smem[];
    const uint32_t sbase = smem_u32(smem);
    const int tid = threadIdx.x;
    const int lane = tid & 31, warp = tid >> 5;
    const int wm = warp >> 2, wn = warp & 3;
    const int g = lane >> 2, q = lane & 3;
    const int numN = N >> 7;
    const int ntiles = K >> 6;
    const int G = gridDim.x;
    const int bid = blockIdx.x;
    if (bid >= numTiles) return;
    const int numMy = (numTiles - bid + G - 1) / G;
    const int myTot = numMy * ntiles;

    // loader rows/groups (fixed per thread)
    const int lrow = tid >> 3, lgrp = tid & 7;
    const uint32_t lsoffA = ((lgrp ^ (lrow & 7)) << 4);

    auto issue_loads = [&](int pos) {
        if (pos < myTot) {
            int w = pos / ntiles;
            int kt = pos - w * ntiles;
            int t = bid + w * G;
            int m0 = (t / numN) << 7;
            int n0 = (t - (t / numN) * numN) << 7;
            const bf16* Ag = A + (size_t)m0 * K + (kt << 6);
            const bf16* Bg = B + (size_t)n0 * K + (kt << 6);
            uint32_t sa = sbase + (pos % 3) * GSTAGE;
            uint32_t sb = sa + 16384;
            #pragma unroll
            for (int i = 0; i < 4; i++) {
                int row = lrow + i * 32;
                uint32_t soff = row * 128 + ((lgrp ^ (row & 7)) << 4);
                cp_async16(sa + soff, Ag + (size_t)row * K + lgrp * 8);
                cp_async16(sb + soff, Bg + (size_t)row * K + lgrp * 8);
            }
        }
        cp_commit();
    };

    float acc[4][4][4];

    issue_loads(0);
    issue_loads(1);

    for (int pos = 0; pos < myTot; pos++) {
        int w = pos / ntiles;
        int kt = pos - w * ntiles;
        cp_wait<1>();
        __syncthreads();
        issue_loads(pos + 2);

        if (kt == 0) {
            #pragma unroll
            for (int i = 0; i < 4; i++)
                #pragma unroll
                for (int j = 0; j < 4; j++)
                    #pragma unroll
                    for (int k = 0; k < 4; k++) acc[i][j][k] = 0.0f;
        }

        uint32_t sa = sbase + (pos % 3) * GSTAGE;
        uint32_t sb = sa + 16384;
        #pragma unroll
        for (int kc = 0; kc < 4; kc++) {
            uint32_t afr[4][4], bfr[4][2];
            int rsel = lane & 15;
            int gsel = kc * 2 + (lane >> 4);
            #pragma unroll
            for (int mt = 0; mt < 4; mt++) {
                int row = wm * 64 + mt * 16 + rsel;
                uint32_t addr = sa + row * 128 + ((gsel ^ (row & 7)) << 4);
                ldsm_x4(afr[mt][0], afr[mt][1], afr[mt][2], afr[mt][3], addr);
            }
            #pragma unroll
            for (int h = 0; h < 2; h++) {
                int row = wn * 32 + h * 16 + rsel;
                uint32_t addr = sb + row * 128 + ((gsel ^ (row & 7)) << 4);
                uint32_t x, y, z, wv;
                ldsm_x4(x, y, z, wv, addr);
                bfr[2 * h][0] = x;     bfr[2 * h][1] = z;
                bfr[2 * h + 1][0] = y; bfr[2 * h + 1][1] = wv;
            }
            #pragma unroll
            for (int mt = 0; mt < 4; mt++)
                #pragma unroll
                for (int nt = 0; nt < 4; nt++)
                    mma_bf16(acc[mt][nt], afr[mt], bfr[nt]);
        }

        if (kt == ntiles - 1) {
            int t = bid + w * G;
            int m0 = (t / numN) << 7;
            int n0 = (t - (t / numN) * numN) << 7;
            #pragma unroll
            for (int mt = 0; mt < 4; mt++) {
                size_t rg = (size_t)m0 + wm * 64 + mt * 16 + g;
                #pragma unroll
                for (int nt = 0; nt < 4; nt++) {
                    int cb = n0 + wn * 32 + nt * 8 + 2 * q;
                    float b0 = bias[cb], b1 = bias[cb + 1];
                    float v0 = acc[mt][nt][0] + b0, v1 = acc[mt][nt][1] + b1;
                    float v2 = acc[mt][nt][2] + b0, v3 = acc[mt][nt][3] + b1;
                    if (GELU) {
                        v0 = gelu_exact(v0); v1 = gelu_exact(v1);
                        v2 = gelu_exact(v2); v3 = gelu_exact(v3);
                    }
                    if constexpr (sizeof(OutT) == 4) {
                        *(float2*)&((float*)C)[rg * N + cb] = make_float2(v0, v1);
                        *(float2*)&((float*)C)[(rg + 8) * N + cb] = make_float2(v2, v3);
                    } else {
                        *(uint32_t*)&((bf16*)C)[rg * N + cb] = f2bf2(v0, v1);
                        *(uint32_t*)&((bf16*)C)[(rg + 8) * N + cb] = f2bf2(v2, v3);
                    }
                }
            }
        }
    }
}

// ================= TN fuse GEMM: A k-major (cat layout), B NT weights =================
#define TNSTAGE 33792          // 64*272 (A) + 16384 (B)
#define TN_SMEM (3 * TNSTAGE)  // 101376
__global__ __launch_bounds__(256, 2) void gemm_fuse_tn(
        const bf16* __restrict__ Acat, const bf16* __restrict__ B,
        const float* __restrict__ bias, float* __restrict__ C) {
    extern __shared__ uint8_t smem[];
    const uint32_t sbase = smem_u32(smem);
    const int tid = threadIdx.x;
    const int lane = tid & 31, warp = tid >> 5;
    const int wm = warp >> 2, wn = warp & 3;
    const int g = lane >> 2, q = lane & 3;
    const int K = 768, N = 256;
    const size_t m0 = (size_t)blockIdx.y * 128;
    const int n0 = blockIdx.x * 128;
    const int bglob = (int)(m0 >> 14);
    const int p0 = (int)(m0 & 16383);
    const bf16* Ag = Acat + ((size_t)bglob * 768) * NHW + p0;
    const bf16* Bg = B + (size_t)n0 * K;
    const int ntiles = 12;

    float acc[4][4][4];
    #pragma unroll
    for (int i = 0; i < 4; i++)
        #pragma unroll
        for (int j = 0; j < 4; j++)
            #pragma unroll
            for (int k = 0; k < 4; k++) acc[i][j][k] = 0.0f;

    auto load_stage = [&](int st, int k0) {
        uint32_t sa = sbase + st * TNSTAGE;
        uint32_t sb = sa + 64 * 272;
        #pragma unroll
        for (int i = 0; i < 4; i++) {
            int id = i * 256 + tid;
            int arow = id >> 4, ach = id & 15;
            cp_async16(sa + arow * 272 + ach * 16,
                       Ag + (size_t)(k0 + arow) * NHW + ach * 8);
            int brow = id >> 3, bgrp = id & 7;
            cp_async16(sb + brow * 128 + ((bgrp ^ (brow & 7)) << 4),
                       Bg + (size_t)brow * K + k0 + bgrp * 8);
        }
    };

    load_stage(0, 0);  cp_commit();
    load_stage(1, 64); cp_commit();
    cp_wait<1>();
    __syncthreads();

    const int atile = lane >> 3;
    const int arr   = lane & 7;
    const int ak_half = (atile >> 1) << 3;
    const int am_half = (atile & 1) << 3;

    for (int kt = 0; kt < ntiles; kt++) {
        if (kt + 2 < ntiles) load_stage((kt + 2) % 3, (kt + 2) << 6);
        cp_commit();

        uint32_t sa = sbase + (kt % 3) * TNSTAGE;
        uint32_t sb = sa + 64 * 272;
        #pragma unroll
        for (int kc = 0; kc < 4; kc++) {
            uint32_t afr[4][4], bfr[4][2];
            int klocal = kc * 16 + ak_half + arr;
            #pragma unroll
            for (int mt = 0; mt < 4; mt++) {
                int moff = wm * 64 + mt * 16 + am_half;
                uint32_t addr = sa + klocal * 272 + moff * 2;
                ldsm_x4_t(afr[mt][0], afr[mt][1], afr[mt][2], afr[mt][3], addr);
            }
            int rsel = lane & 15;
            int gsel = kc * 2 + (lane >> 4);
            #pragma unroll
            for (int h = 0; h < 2; h++) {
                int row = wn * 32 + h * 16 + rsel;
                uint32_t addr = sb + row * 128 + ((gsel ^ (row & 7)) << 4);
                uint32_t x, y, z, w;
                ldsm_x4(x, y, z, w, addr);
                bfr[2 * h][0] = x;     bfr[2 * h][1] = z;
                bfr[2 * h + 1][0] = y; bfr[2 * h + 1][1] = w;
            }
            #pragma unroll
            for (int mt = 0; mt < 4; mt++)
                #pragma unroll
                for (int nt = 0; nt < 4; nt++)
                    mma_bf16(acc[mt][nt], afr[mt], bfr[nt]);
        }
        cp_wait<1>();
        __syncthreads();
    }

    #pragma unroll
    for (int mt = 0; mt < 4; mt++) {
        size_t rg = m0 + wm * 64 + mt * 16 + g;
        #pragma unroll
        for (int nt = 0; nt < 4; nt++) {
            int cb = n0 + wn * 32 + nt * 8 + 2 * q;
            float b0 = bias[cb], b1 = bias[cb + 1];
            *(float2*)&C[rg * N + cb] =
                make_float2(acc[mt][nt][0] + b0, acc[mt][nt][1] + b1);
            *(float2*)&C[(rg + 8) * N + cb] =
                make_float2(acc[mt][nt][2] + b0, acc[mt][nt][3] + b1);
        }
    }
}

// ================= tensor-core attention, L=64, D=32 (mma.sync) =================
__global__ void attn_kernel(const bf16* __restrict__ QKV, bf16* __restrict__ O) {
    __shared__ uint32_t sq[64 * 24];
    __shared__ uint32_t sk[64 * 24];
    __shared__ uint32_t sv[32 * 40];
    int wh = blockIdx.x;
    int win = wh >> 3, head = wh & 7;
    int tid = threadIdx.x;
    int warp = tid >> 5, lane = tid & 31;
    int g = lane >> 2, q = lane & 3;
    const bf16* base = QKV + (size_t)win * 64 * 768 + head * 32;

    {
        int r = tid >> 1, ch = tid & 1;
        int sw = ch ^ ((r >> 2) & 1);
        const bf16* src = base + (size_t)r * 768 + ch * 16;
        uint4 lo = *(const uint4*)src;
        uint4 hi = *(const uint4*)(src + 8);
        uint2* dst = (uint2*)(sq + r * 24 + sw * 8);
        dst[0] = make_uint2(lo.x, hi.x); dst[1] = make_uint2(lo.y, hi.y);
        dst[2] = make_uint2(lo.z, hi.z); dst[3] = make_uint2(lo.w, hi.w);
        lo = *(const uint4*)(src + 256);
        hi = *(const uint4*)(src + 264);
        dst = (uint2*)(sk + r * 24 + sw * 8);
        dst[0] = make_uint2(lo.x, hi.x); dst[1] = make_uint2(lo.y, hi.y);
        dst[2] = make_uint2(lo.z, hi.z); dst[3] = make_uint2(lo.w, hi.w);
    }
    {
        int jp = tid >> 2, d0 = (tid & 3) * 8;
        int j = jp * 2;
        const bf16* v0p = base + (size_t)j * 768 + 512 + d0;
        uint4 v0 = *(const uint4*)v0p;
        uint4 v1 = *(const uint4*)(v0p + 768);
        uint32_t u0[4] = {v0.x, v0.y, v0.z, v0.w};
        uint32_t u1[4] = {v1.x, v1.y, v1.z, v1.w};
        int cj = jp >> 3;
        int pr = jp & 7;
        int wp = ((pr & 3) << 1) | (pr >> 2);
        #pragma unroll
        for (int m = 0; m < 4; m++) {
            int d = d0 + 2 * m;
            uint32_t loP = (u0[m] & 0xffffu) | (u1[m] << 16);
            uint32_t hiP = (u0[m] >> 16) | (u1[m] & 0xffff0000u);
            sv[d * 40 + ((cj ^ ((d >> 2) & 3)) * 8) + wp] = loP;
            sv[(d + 1) * 40 + ((cj ^ (((d + 1) >> 2) & 3)) * 8) + wp] = hiP;
        }
    }
    __syncthreads();

    float sacc[8][4];
    #pragma unroll
    for (int nt = 0; nt < 8; nt++)
        #pragma unroll
        for (int i = 0; i < 4; i++) sacc[nt][i] = 0.0f;
    #pragma unroll
    for (int kc = 0; kc < 2; kc++) {
        int r0 = warp * 16 + g, r1 = r0 + 8;
        uint2 lo = *(uint2*)&sq[r0 * 24 + ((kc ^ ((r0 >> 2) & 1)) * 8) + 2 * q];
        uint2 hi = *(uint2*)&sq[r1 * 24 + ((kc ^ ((r1 >> 2) & 1)) * 8) + 2 * q];
        uint32_t a[4] = {lo.x, hi.x, lo.y, hi.y};
        #pragma unroll
        for (int nt = 0; nt < 8; nt++) {
            int rn = nt * 8 + g;
            uint2 bb = *(uint2*)&sk[rn * 24 + ((kc ^ ((rn >> 2) & 1)) * 8) + 2 * q];
            uint32_t bfv[2] = {bb.x, bb.y};
            mma_bf16(sacc[nt], a, bfv);
        }
    }

    const float scale = 0.17677669529663687f;
    #pragma unroll
    for (int nt = 0; nt < 8; nt++)
        #pragma unroll
        for (int i = 0; i < 4; i++) sacc[nt][i] *= scale;
    float mx0 = -1e30f, mx1 = -1e30f;
    #pragma unroll
    for (int nt = 0; nt < 8; nt++) {
        mx0 = fmaxf(mx0, fmaxf(sacc[nt][0], sacc[nt][1]));
        mx1 = fmaxf(mx1, fmaxf(sacc[nt][2], sacc[nt][3]));
    }
    mx0 = fmaxf(mx0, __shfl_xor_sync(0xffffffff, mx0, 1));
    mx0 = fmaxf(mx0, __shfl_xor_sync(0xffffffff, mx0, 2));
    mx1 = fmaxf(mx1, __shfl_xor_sync(0xffffffff, mx1, 1));
    mx1 = fmaxf(mx1, __shfl_xor_sync(0xffffffff, mx1, 2));
    float sum0 = 0.0f, sum1 = 0.0f;
    #pragma unroll
    for (int nt = 0; nt < 8; nt++) {
        sacc[nt][0] = __expf(sacc[nt][0] - mx0);
        sacc[nt][1] = __expf(sacc[nt][1] - mx0);
        sacc[nt][2] = __expf(sacc[nt][2] - mx1);
        sacc[nt][3] = __expf(sacc[nt][3] - mx1);
        sum0 += sacc[nt][0] + sacc[nt][1];
        sum1 += sacc[nt][2] + sacc[nt][3];
    }
    sum0 += __shfl_xor_sync(0xffffffff, sum0, 1);
    sum0 += __shfl_xor_sync(0xffffffff, sum0, 2);
    sum1 += __shfl_xor_sync(0xffffffff, sum1, 1);
    sum1 += __shfl_xor_sync(0xffffffff, sum1, 2);
    float inv0 = 1.0f / sum0, inv1 = 1.0f / sum1;
    #pragma unroll
    for (int nt = 0; nt < 8; nt++) {
        sacc[nt][0] *= inv0; sacc[nt][1] *= inv0;
        sacc[nt][2] *= inv1; sacc[nt][3] *= inv1;
    }

    float oacc[4][4];
    #pragma unroll
    for (int nt = 0; nt < 4; nt++)
        #pragma unroll
        for (int i = 0; i < 4; i++) oacc[nt][i] = 0.0f;
    #pragma unroll
    for (int kc = 0; kc < 4; kc++) {
        uint32_t a[4];
        a[0] = f2bf2(sacc[2 * kc][0], sacc[2 * kc][1]);
        a[1] = f2bf2(sacc[2 * kc][2], sacc[2 * kc][3]);
        a[2] = f2bf2(sacc[2 * kc + 1][0], sacc[2 * kc + 1][1]);
        a[3] = f2bf2(sacc[2 * kc + 1][2], sacc[2 * kc + 1][3]);
        #pragma unroll
        for (int nt = 0; nt < 4; nt++) {
            int rn = nt * 8 + g;
            uint2 bb = *(uint2*)&sv[rn * 40 + ((kc ^ ((rn >> 2) & 3)) * 8) + 2 * q];
            uint32_t bfv[2] = {bb.x, bb.y};
            mma_bf16(oacc[nt], a, bfv);
        }
    }

    int row0 = win * 64 + warp * 16 + g;
    bf16* o0 = O + (size_t)row0 * NC + head * 32;
    bf16* o1 = o0 + 8 * NC;
    #pragma unroll
    for (int nt = 0; nt < 4; nt++) {
        int cb = nt * 8 + 2 * q;
        *(uint32_t*)&o0[cb] = f2bf2(oacc[nt][0], oacc[nt][1]);
        *(uint32_t*)&o1[cb] = f2bf2(oacc[nt][2], oacc[nt][3]);
    }
}

// ---------------- launch ----------------
extern "C" void kernel_launch(void* const* d_in, const int* in_sizes, int n_in,
                              void* d_out, int out_size) {
    const float* x      = (const float*)d_in[0];
    const float* w1     = (const float*)d_in[1];
    const float* b1     = (const float*)d_in[2];
    const float* w2     = (const float*)d_in[3];
    const float* b2     = (const float*)d_in[4];
    const float* w3     = (const float*)d_in[5];
    const float* b3     = (const float*)d_in[6];
    const float* wf     = (const float*)d_in[7];
    const float* bf     = (const float*)d_in[8];
    const float* gw     = (const float*)d_in[9];
    const float* bw     = (const float*)d_in[10];
    const float* wqkv_w = (const float*)d_in[11];
    const float* bqkv_w = (const float*)d_in[12];
    const float* wo_w   = (const float*)d_in[13];
    const float* bo_w   = (const float*)d_in[14];
    const float* gg     = (const float*)d_in[15];
    const float* bg     = (const float*)d_in[16];
    const float* wqkv_g = (const float*)d_in[17];
    const float* bqkv_g = (const float*)d_in[18];
    const float* wo_g   = (const float*)d_in[19];
    const float* bo_g   = (const float*)d_in[20];
    const float* gm     = (const float*)d_in[21];
    const float* bm     = (const float*)d_in[22];
    const float* m1w    = (const float*)d_in[23];
    const float* m1b    = (const float*)d_in[24];
    const float* m2w    = (const float*)d_in[25];
    const float* m2b    = (const float*)d_in[26];
    float* out = (float*)d_out;

    static bool attrs_set = false;
    if (!attrs_set) {
        cudaFuncSetAttribute(gemm_bf16_nt<float, false>,
                             cudaFuncAttributeMaxDynamicSharedMemorySize, GEMM_SMEM);
        cudaFuncSetAttribute(gemm_bf16_nt<bf16, false>,
                             cudaFuncAttributeMaxDynamicSharedMemorySize, GEMM_SMEM);
        cudaFuncSetAttribute(gemm_bf16_nt<bf16, true>,
                             cudaFuncAttributeMaxDynamicSharedMemorySize, GEMM_SMEM);
        cudaFuncSetAttribute(gemm_fuse_tn,
                             cudaFuncAttributeMaxDynamicSharedMemorySize, TN_SMEM);
        attrs_set = true;
    }

    void *p_cat, *p_xm, *p_xtok, *p_tok, *p_qkv, *p_att, *p_proj, *p_h1, *p_wb;
    cudaGetSymbolAddress(&p_cat, g_cat);
    cudaGetSymbolAddress(&p_xm, g_xm);
    cudaGetSymbolAddress(&p_xtok, g_xtok);
    cudaGetSymbolAddress(&p_tok, g_tok);
    cudaGetSymbolAddress(&p_qkv, g_qkv);
    cudaGetSymbolAddress(&p_att, g_att);
    cudaGetSymbolAddress(&p_proj, g_proj);
    cudaGetSymbolAddress(&p_h1, g_h1);
    cudaGetSymbolAddress(&p_wb, g_wb);
    bf16* cat  = (bf16*)p_cat;
    float* xm  = (float*)p_xm;    float* xtok = (float*)p_xtok;
    bf16* tok  = (bf16*)p_tok;    bf16* qkv  = (bf16*)p_qkv;
    bf16* att  = (bf16*)p_att;    bf16* proj = (bf16*)p_proj;
    bf16* h1   = (bf16*)p_h1;     bf16* wb   = (bf16*)p_wb;

    // all weight conversions in one launch
    cvt_all<<<1216, 256>>>(wf, wqkv_w, wqkv_g, wo_w, wo_g, m1w, m2w, wb);

    // depthwise convs -> cat (bf16, k-major); x -> token-major fp32
    dwconv3_kernel<<<dim3(16, NC, NB), 256>>>(x, w1, b1, w2, b2, w3, b3);
    to_tok<<<dim3(256, 4, NB), 256>>>(x, xtok);

    // 1x1 fuse as TN GEMM (A read k-major) -> xm (fp32)
    gemm_fuse_tn<<<dim3(2, 1024), 256, TN_SMEM>>>(cat, wb + OFF_WF, bf, xm);

    // ---- window branch ----
    ln_perm<<<16384, 256>>>(xm, gw, bw, tok, 0);
    gemm_bf16_nt<bf16, false><<<NPERSIST, 256, GEMM_SMEM>>>(tok, wb + OFF_QKVW, bqkv_w, qkv, 768, 256, 6144);
    attn_kernel<<<16384, 128>>>(qkv, att);
    gemm_bf16_nt<bf16, false><<<NPERSIST, 256, GEMM_SMEM>>>(att, wb + OFF_WOW, bo_w, proj, 256, 256, 2048);
    resadd_ln<<<16384, 256>>>(xtok, proj, xm, gg, bg, tok, 0, 1);

    // ---- grid branch ----
    gemm_bf16_nt<bf16, false><<<NPERSIST, 256, GEMM_SMEM>>>(tok, wb + OFF_QKVG, bqkv_g, qkv, 768, 256, 6144);
    attn_kernel<<<16384, 128>>>(qkv, att);
    gemm_bf16_nt<bf16, false><<<NPERSIST, 256, GEMM_SMEM>>>(att, wb + OFF_WOG, bo_g, proj, 256, 256, 2048);
    resadd_ln<<<16384, 256>>>(xm, proj, xm, gm, bm, tok, 1, 2);

    // ---- MLP ----
    gemm_bf16_nt<bf16, true ><<<NPERSIST, 256, GEMM_SMEM>>>(tok, wb + OFF_M1, m1b, h1, 1024, 256, 8192);
    gemm_bf16_nt<bf16, false><<<NPERSIST, 256, GEMM_SMEM>>>(h1, wb + OFF_M2, m2b, proj, 256, 1024, 2048);
    from_tok_add<<<dim3(256, 4, NB), 256>>>(xm, proj, out);
}

// round 14
// speedup vs baseline: 1.0469x; 1.0469x over previous
#include <cuda_runtime.h>
#include <cuda_bf16.h>
#include <math.h>
#include <stdint.h>

// ---------------- problem constants ----------------
#define NB   8
#define NC   256
#define NHW  16384     // 128*128
#define NTOK 131072    // NB*NHW
#define NPERSIST 304   // 2 CTAs/SM x 152 SMs (GB300)

typedef __nv_bfloat16 bf16;

// ---------------- scratch (device globals) ----------------
__device__ bf16  g_cat [(size_t)NB * 768 * NHW];   // [B,3C,HW] bf16 (k-major)
__device__ float g_xm  [(size_t)NTOK * NC];        // residual stream (fp32)
__device__ float g_xtok[(size_t)NTOK * NC];        // x token-major (fp32)
__device__ bf16  g_tok [(size_t)NTOK * NC];        // LN'd tokens bf16
__device__ bf16  g_qkv [(size_t)NTOK * 768];
__device__ bf16  g_att [(size_t)NTOK * NC];
__device__ bf16  g_proj[(size_t)NTOK * NC];        // projection outputs (bf16)
__device__ bf16  g_h1  [(size_t)NTOK * 1024];
__device__ bf16  g_wb  [1245184];                  // all weights converted to bf16

// weight offsets in g_wb (elements)
#define OFF_WF   0
#define OFF_QKVW 196608
#define OFF_QKVG 393216
#define OFF_WOW  589824
#define OFF_WOG  655360
#define OFF_M1   720896
#define OFF_M2   983040

// ---------------- helpers ----------------
__device__ __forceinline__ float gelu_exact(float x) {
    return 0.5f * x * (1.0f + erff(x * 0.70710678118654752f));
}
__device__ __forceinline__ uint32_t f2bf2(float a, float b) {
    __nv_bfloat162 h = __floats2bfloat162_rn(a, b);
    return *reinterpret_cast<uint32_t*>(&h);
}
__device__ __forceinline__ float2 bf2f(uint32_t w) {
    __nv_bfloat162 h = *reinterpret_cast<__nv_bfloat162*>(&w);
    return __bfloat1622float2(h);
}
__device__ __forceinline__ void mma_bf16(float* d, const uint32_t* a, const uint32_t* b) {
    asm volatile(
        "mma.sync.aligned.m16n8k16.row.col.f32.bf16.bf16.f32 "
        "{%0,%1,%2,%3}, {%4,%5,%6,%7}, {%8,%9}, {%0,%1,%2,%3};"
        : "+f"(d[0]), "+f"(d[1]), "+f"(d[2]), "+f"(d[3])
        : "r"(a[0]), "r"(a[1]), "r"(a[2]), "r"(a[3]), "r"(b[0]), "r"(b[1]));
}
__device__ __forceinline__ uint32_t smem_u32(const void* p) {
    return (uint32_t)__cvta_generic_to_shared(p);
}
__device__ __forceinline__ void cp_async16(uint32_t s, const void* gp) {
    asm volatile("cp.async.cg.shared.global [%0], [%1], 16;" :: "r"(s), "l"(gp));
}
__device__ __forceinline__ void cp_commit() {
    asm volatile("cp.async.commit_group;");
}
template<int W> __device__ __forceinline__ void cp_wait() {
    asm volatile("cp.async.wait_group %0;" :: "n"(W));
}
__device__ __forceinline__ void ldsm_x4(uint32_t& a, uint32_t& b, uint32_t& c, uint32_t& d,
                                        uint32_t addr) {
    asm volatile("ldmatrix.sync.aligned.m8n8.x4.shared.b16 {%0,%1,%2,%3}, [%4];"
        : "=r"(a), "=r"(b), "=r"(c), "=r"(d) : "r"(addr));
}
__device__ __forceinline__ void ldsm_x4_t(uint32_t& a, uint32_t& b, uint32_t& c, uint32_t& d,
                                          uint32_t addr) {
    asm volatile("ldmatrix.sync.aligned.m8n8.x4.trans.shared.b16 {%0,%1,%2,%3}, [%4];"
        : "=r"(a), "=r"(b), "=r"(c), "=r"(d) : "r"(addr));
}

// ---------------- merged weight fp32 -> bf16 ----------------
__global__ void cvt_all(const float* __restrict__ wf, const float* __restrict__ qw,
                        const float* __restrict__ qg, const float* __restrict__ ow,
                        const float* __restrict__ og, const float* __restrict__ m1,
                        const float* __restrict__ m2, bf16* __restrict__ d) {
    int i = blockIdx.x * 256 + threadIdx.x;   // quad index
    if (i >= 311296) return;
    const float* src;
    int local;
    if (i < 49152)        { src = wf; local = i; }
    else if (i < 98304)   { src = qw; local = i - 49152; }
    else if (i < 147456)  { src = qg; local = i - 98304; }
    else if (i < 163840)  { src = ow; local = i - 147456; }
    else if (i < 180224)  { src = og; local = i - 163840; }
    else if (i < 245760)  { src = m1; local = i - 180224; }
    else                  { src = m2; local = i - 245760; }
    float4 v = *(const float4*)(src + (size_t)local * 4);
    *(uint2*)(d + (size_t)i * 4) = make_uint2(f2bf2(v.x, v.y), f2bf2(v.z, v.w));
}

// ---------------- 1) fused depthwise convs (3x3,5x5,7x7) -> bf16 cat ----------------
__global__ void dwconv3_kernel(const float* __restrict__ X,
                               const float* __restrict__ w1, const float* __restrict__ b1,
                               const float* __restrict__ w2, const float* __restrict__ b2,
                               const float* __restrict__ w3, const float* __restrict__ b3) {
    __shared__ float sx[38][39];
    __shared__ float swt[83];
    int c = blockIdx.y, b = blockIdx.z;
    int tile = blockIdx.x;
    int ty0 = (tile >> 2) * 32, tx0 = (tile & 3) * 32;
    const float* Xp = X + ((size_t)b * NC + c) * NHW;
    int tid = threadIdx.x;

    if (tid < 9)       swt[tid] = w1[c * 9 + tid];
    else if (tid < 34) swt[tid] = w2[c * 25 + (tid - 9)];
    else if (tid < 83) swt[tid] = w3[c * 49 + (tid - 34)];

    for (int i = tid; i < 38 * 38; i += 256) {
        int iy = i / 38, ix = i - iy * 38;
        int gy = ty0 + iy - 3, gx = tx0 + ix - 3;
        float v = 0.0f;
        if (gy >= 0 && gy < 128 && gx >= 0 && gx < 128) v = Xp[gy * 128 + gx];
        sx[iy][ix] = v;
    }
    __syncthreads();

    float bb1 = b1[c], bb2 = b2[c], bb3 = b3[c];
    size_t ob1 = ((size_t)b * 768 + c) * NHW;
    size_t ob2 = ((size_t)b * 768 + 256 + c) * NHW;
    size_t ob3 = ((size_t)b * 768 + 512 + c) * NHW;

    #pragma unroll
    for (int sub = 0; sub < 4; sub++) {
        int oy = (tid >> 5) + sub * 8;
        int ox = (tid & 31);
        int cy = oy + 3, cx = ox + 3;
        float a1 = bb1, a2 = bb2, a3 = bb3;
        #pragma unroll
        for (int dy = -3; dy <= 3; dy++) {
            #pragma unroll
            for (int dx = -3; dx <= 3; dx++) {
                float v = sx[cy + dy][cx + dx];
                a3 += v * swt[34 + (dy + 3) * 7 + (dx + 3)];
                if (dy >= -2 && dy <= 2 && dx >= -2 && dx <= 2)
                    a2 += v * swt[9 + (dy + 2) * 5 + (dx + 2)];
                if (dy >= -1 && dy <= 1 && dx >= -1 && dx <= 1)
                    a1 += v * swt[(dy + 1) * 3 + (dx + 1)];
            }
        }
        int po = (ty0 + oy) * 128 + tx0 + ox;
        g_cat[ob1 + po] = __float2bfloat16_rn(a1);
        g_cat[ob2 + po] = __float2bfloat16_rn(a2);
        g_cat[ob3 + po] = __float2bfloat16_rn(a3);
    }
}

// ---------------- transpose x [B,C,HW] -> token-major fp32 ----------------
__global__ void to_tok(const float* __restrict__ X, float* __restrict__ T) {
    __shared__ float sm[64][65];
    int p0 = blockIdx.x * 64, c0 = blockIdx.y * 64, b = blockIdx.z;
    int tid = threadIdx.x;
    #pragma unroll
    for (int it = 0; it < 4; it++) {
        int c = it * 16 + (tid >> 4);
        int p4 = (tid & 15) * 4;
        float4 v = *(const float4*)&X[((size_t)(b * NC + c0 + c)) * NHW + p0 + p4];
        sm[c][p4 + 0] = v.x; sm[c][p4 + 1] = v.y; sm[c][p4 + 2] = v.z; sm[c][p4 + 3] = v.w;
    }
    __syncthreads();
    #pragma unroll
    for (int it = 0; it < 4; it++) {
        int p = it * 16 + (tid >> 4);
        int c4 = (tid & 15) * 4;
        float4 v = make_float4(sm[c4][p], sm[c4 + 1][p], sm[c4 + 2][p], sm[c4 + 3][p]);
        *(float4*)&T[((size_t)(b * NHW + p0 + p)) * NC + c0 + c4] = v;
    }
}

// ---------------- final: out[b,c,p] = R[t][c] + P[t][c] (P bf16), transposed ----------------
__global__ void from_tok_add(const float* __restrict__ R, const bf16* __restrict__ P,
                             float* __restrict__ O) {
    __shared__ float sm[64][65];
    int p0 = blockIdx.x * 64, c0 = blockIdx.y * 64, b = blockIdx.z;
    int tid = threadIdx.x;
    #pragma unroll
    for (int it = 0; it < 4; it++) {
        int p = it * 16 + (tid >> 4);
        int c4 = (tid & 15) * 4;
        size_t row = ((size_t)(b * NHW + p0 + p)) * NC + c0 + c4;
        float4 a = *(const float4*)&R[row];
        uint2 qw = *(const uint2*)&P[row];
        float2 qa = bf2f(qw.x), qb = bf2f(qw.y);
        sm[c4 + 0][p] = a.x + qa.x; sm[c4 + 1][p] = a.y + qa.y;
        sm[c4 + 2][p] = a.z + qb.x; sm[c4 + 3][p] = a.w + qb.y;
    }
    __syncthreads();
    #pragma unroll
    for (int it = 0; it < 4; it++) {
        int c = it * 16 + (tid >> 4);
        int p4 = (tid & 15) * 4;
        float4 v = make_float4(sm[c][p4], sm[c][p4 + 1], sm[c][p4 + 2], sm[c][p4 + 3]);
        *(float4*)&O[((size_t)(b * NC + c0 + c)) * NHW + p0 + p4] = v;
    }
}

// ---------------- fused LN + permute -> bf16 tokens (first LN) ----------------
__global__ void ln_perm(const float* __restrict__ R, const float* __restrict__ gam,
                        const float* __restrict__ bet, bf16* __restrict__ T, int mode) {
    int warp = threadIdx.x >> 5, lane = threadIdx.x & 31;
    int t = blockIdx.x * 8 + warp;
    int b = t >> 14, r = t & 16383;
    int p;
    if (mode == 2) p = r;
    else {
        int win = r >> 6, pos = r & 63;
        int wy = win >> 4, wx = win & 15;
        int py = pos >> 3, px = pos & 7;
        if (mode == 0) p = (wy * 8 + py) * 128 + wx * 8 + px;
        else           p = (py * 16 + wy) * 128 + px * 16 + wx;
    }
    const float* src = R + ((size_t)b * NHW + p) * NC;
    float4 v0 = *(const float4*)(src + lane * 4);
    float4 v1 = *(const float4*)(src + 128 + lane * 4);
    float s  = v0.x + v0.y + v0.z + v0.w + v1.x + v1.y + v1.z + v1.w;
    float s2 = v0.x * v0.x + v0.y * v0.y + v0.z * v0.z + v0.w * v0.w
             + v1.x * v1.x + v1.y * v1.y + v1.z * v1.z + v1.w * v1.w;
    #pragma unroll
    for (int o = 16; o; o >>= 1) {
        s  += __shfl_xor_sync(0xffffffff, s, o);
        s2 += __shfl_xor_sync(0xffffffff, s2, o);
    }
    float m = s * (1.0f / NC);
    float rs = rsqrtf(s2 * (1.0f / NC) - m * m + 1e-5f);
    float4 g0 = *(const float4*)(gam + lane * 4);
    float4 g1 = *(const float4*)(gam + 128 + lane * 4);
    float4 b0 = *(const float4*)(bet + lane * 4);
    float4 b1 = *(const float4*)(bet + 128 + lane * 4);
    bf16* dst = T + (size_t)t * NC;
    float o0x = (v0.x - m) * rs * g0.x + b0.x, o0y = (v0.y - m) * rs * g0.y + b0.y;
    float o0z = (v0.z - m) * rs * g0.z + b0.z, o0w = (v0.w - m) * rs * g0.w + b0.w;
    float o1x = (v1.x - m) * rs * g1.x + b1.x, o1y = (v1.y - m) * rs * g1.y + b1.y;
    float o1z = (v1.z - m) * rs * g1.z + b1.z, o1w = (v1.w - m) * rs * g1.w + b1.w;
    *(uint2*)(dst + lane * 4)       = make_uint2(f2bf2(o0x, o0y), f2bf2(o0z, o0w));
    *(uint2*)(dst + 128 + lane * 4) = make_uint2(f2bf2(o1x, o1y), f2bf2(o1z, o1w));
}

// ---------------- fused residual-add (permuted bf16 proj) + LN + permute-out ----------------
__global__ void resadd_ln(const float* __restrict__ base, const bf16* __restrict__ P,
                          float* __restrict__ Rout, const float* __restrict__ gam,
                          const float* __restrict__ bet, bf16* __restrict__ T,
                          int addmode, int lnmode) {
    int warp = threadIdx.x >> 5, lane = threadIdx.x & 31;
    int t = blockIdx.x * 8 + warp;
    int b = t >> 14, p = t & 16383;
    int h = p >> 7, w = p & 127;
    int tp;
    if (addmode == 0) {
        int win = (h >> 3) * 16 + (w >> 3);
        int pos = (h & 7) * 8 + (w & 7);
        tp = (b << 14) + win * 64 + pos;
    } else {
        int K2 = h >> 3, K1 = ((h & 7) << 1) | (w >> 6);
        int S1 = (w >> 3) & 7, S2 = w & 7;
        tp = (b << 14) + (K1 * 16 + K2) * 64 + S1 * 8 + S2;
    }
    const float* pb = base + (size_t)t * NC;
    const bf16* pp = P + (size_t)tp * NC;
    float4 v0 = *(const float4*)(pb + lane * 4);
    float4 v1 = *(const float4*)(pb + 128 + lane * 4);
    uint2 qw0 = *(const uint2*)(pp + lane * 4);
    uint2 qw1 = *(const uint2*)(pp + 128 + lane * 4);
    float2 qa = bf2f(qw0.x), qb = bf2f(qw0.y);
    float2 qc = bf2f(qw1.x), qd = bf2f(qw1.y);
    v0.x += qa.x; v0.y += qa.y; v0.z += qb.x; v0.w += qb.y;
    v1.x += qc.x; v1.y += qc.y; v1.z += qd.x; v1.w += qd.y;
    float* po = Rout + (size_t)t * NC;
    *(float4*)(po + lane * 4) = v0;
    *(float4*)(po + 128 + lane * 4) = v1;

    float s  = v0.x + v0.y + v0.z + v0.w + v1.x + v1.y + v1.z + v1.w;
    float s2 = v0.x * v0.x + v0.y * v0.y + v0.z * v0.z + v0.w * v0.w
             + v1.x * v1.x + v1.y * v1.y + v1.z * v1.z + v1.w * v1.w;
    #pragma unroll
    for (int o = 16; o; o >>= 1) {
        s  += __shfl_xor_sync(0xffffffff, s, o);
        s2 += __shfl_xor_sync(0xffffffff, s2, o);
    }
    float m = s * (1.0f / NC);
    float rs = rsqrtf(s2 * (1.0f / NC) - m * m + 1e-5f);
    float4 g0 = *(const float4*)(gam + lane * 4);
    float4 g1 = *(const float4*)(gam + 128 + lane * 4);
    float4 b0 = *(const float4*)(bet + lane * 4);
    float4 b1 = *(const float4*)(bet + 128 + lane * 4);
    int tout;
    if (lnmode == 2) tout = t;
    else tout = (b << 14) + ((h & 15) * 16 + (w & 15)) * 64 + (h >> 4) * 8 + (w >> 4);
    bf16* dst = T + (size_t)tout * NC;
    float o0x = (v0.x - m) * rs * g0.x + b0.x, o0y = (v0.y - m) * rs * g0.y + b0.y;
    float o0z = (v0.z - m) * rs * g0.z + b0.z, o0w = (v0.w - m) * rs * g0.w + b0.w;
    float o1x = (v1.x - m) * rs * g1.x + b1.x, o1y = (v1.y - m) * rs * g1.y + b1.y;
    float o1z = (v1.z - m) * rs * g1.z + b1.z, o1w = (v1.w - m) * rs * g1.w + b1.w;
    *(uint2*)(dst + lane * 4)       = make_uint2(f2bf2(o0x, o0y), f2bf2(o0z, o0w));
    *(uint2*)(dst + 128 + lane * 4) = make_uint2(f2bf2(o1x, o1y), f2bf2(o1z, o1w));
}

// ================= persistent bf16 NT GEMM v2: division-free cursors =================
// C[M,N] = A[M,K] * B[N,K]^T + bias[n]; 128x128 tiles, BK=64, 8 warps (2x4).
// 304 persistent CTAs; continuous cp.async pipeline across tile boundaries.
// Cursors advance by increment+wrap; t/numN only once per tile.
#define GSTAGE 32768
#define GEMM_SMEM 98304
template<typename OutT, bool GELU>
__global__ __launch_bounds__(256, 2) void gemm_bf16_nt(
        const bf16* __restrict__ A, const bf16* __restrict__ B,
        const float* __restrict__ bias, OutT* __restrict__ C,
        int N, int K, int numTiles) {
    extern __shared__ uint8_t smem[];
    const uint32_t sbase = smem_u32(smem);
    const int tid = threadIdx.x;
    const int lane = tid & 31, warp = tid >> 5;
    const int wm = warp >> 2, wn = warp & 3;
    const int g = lane >> 2, q = lane & 3;
    const int numN = N >> 7;
    const int ntiles = K >> 6;
    const int G = gridDim.x;
    const int bid = blockIdx.x;

    const int lrow = tid >> 3, lgrp = tid & 7;

    // load cursor (division only at tile transitions)
    int tld = bid, ktld = 0, sld = 0;
    int mld = (tld / numN) << 7;
    int nld = (tld - (tld / numN) * numN) << 7;

    auto issue_next = [&]() {
        if (tld < numTiles) {
            const bf16* Ag = A + (size_t)mld * K + (ktld << 6);
            const bf16* Bg = B + (size_t)nld * K + (ktld << 6);
            uint32_t sa = sbase + sld * GSTAGE;
            uint32_t sb = sa + 16384;
            #pragma unroll
            for (int i = 0; i < 4; i++) {
                int row = lrow + i * 32;
                uint32_t soff = row * 128 + ((lgrp ^ (row & 7)) << 4);
                cp_async16(sa + soff, Ag + (size_t)row * K + lgrp * 8);
                cp_async16(sb + soff, Bg + (size_t)row * K + lgrp * 8);
            }
            if (++ktld == ntiles) {
                ktld = 0;
                tld += G;
                if (tld < numTiles) {
                    int mi = tld / numN;
                    mld = mi << 7;
                    nld = (tld - mi * numN) << 7;
                }
            }
            if (++sld == 3) sld = 0;
        }
        cp_commit();
    };

    issue_next();
    issue_next();

    float acc[4][4][4];
    int scomp = 0;
    for (int tc = bid; tc < numTiles; tc += G) {
        int mi = tc / numN;
        int m0 = mi << 7;
        int n0 = (tc - mi * numN) << 7;
        #pragma unroll
        for (int i = 0; i < 4; i++)
            #pragma unroll
            for (int j = 0; j < 4; j++)
                #pragma unroll
                for (int k = 0; k < 4; k++) acc[i][j][k] = 0.0f;

        for (int kt = 0; kt < ntiles; kt++) {
            cp_wait<1>();
            __syncthreads();
            issue_next();

            uint32_t sa = sbase + scomp * GSTAGE;
            uint32_t sb = sa + 16384;
            if (++scomp == 3) scomp = 0;
            #pragma unroll
            for (int kc = 0; kc < 4; kc++) {
                uint32_t afr[4][4], bfr[4][2];
                int rsel = lane & 15;
                int gsel = kc * 2 + (lane >> 4);
                #pragma unroll
                for (int mt = 0; mt < 4; mt++) {
                    int row = wm * 64 + mt * 16 + rsel;
                    uint32_t addr = sa + row * 128 + ((gsel ^ (row & 7)) << 4);
                    ldsm_x4(afr[mt][0], afr[mt][1], afr[mt][2], afr[mt][3], addr);
                }
                #pragma unroll
                for (int h = 0; h < 2; h++) {
                    int row = wn * 32 + h * 16 + rsel;
                    uint32_t addr = sb + row * 128 + ((gsel ^ (row & 7)) << 4);
                    uint32_t x, y, z, wv;
                    ldsm_x4(x, y, z, wv, addr);
                    bfr[2 * h][0] = x;     bfr[2 * h][1] = z;
                    bfr[2 * h + 1][0] = y; bfr[2 * h + 1][1] = wv;
                }
                #pragma unroll
                for (int mt = 0; mt < 4; mt++)
                    #pragma unroll
                    for (int nt = 0; nt < 4; nt++)
                        mma_bf16(acc[mt][nt], afr[mt], bfr[nt]);
            }
        }

        // epilogue: registers -> global, no smem, no sync
        #pragma unroll
        for (int mt = 0; mt < 4; mt++) {
            size_t rg = (size_t)m0 + wm * 64 + mt * 16 + g;
            #pragma unroll
            for (int nt = 0; nt < 4; nt++) {
                int cb = n0 + wn * 32 + nt * 8 + 2 * q;
                float b0 = bias[cb], b1 = bias[cb + 1];
                float v0 = acc[mt][nt][0] + b0, v1 = acc[mt][nt][1] + b1;
                float v2 = acc[mt][nt][2] + b0, v3 = acc[mt][nt][3] + b1;
                if (GELU) {
                    v0 = gelu_exact(v0); v1 = gelu_exact(v1);
                    v2 = gelu_exact(v2); v3 = gelu_exact(v3);
                }
                if constexpr (sizeof(OutT) == 4) {
                    *(float2*)&((float*)C)[rg * N + cb] = make_float2(v0, v1);
                    *(float2*)&((float*)C)[(rg + 8) * N + cb] = make_float2(v2, v3);
                } else {
                    *(uint32_t*)&((bf16*)C)[rg * N + cb] = f2bf2(v0, v1);
                    *(uint32_t*)&((bf16*)C)[(rg + 8) * N + cb] = f2bf2(v2, v3);
                }
            }
        }
    }
}

// ================= TN fuse GEMM: A k-major (cat layout), B NT weights =================
#define TNSTAGE 33792          // 64*272 (A) + 16384 (B)
#define TN_SMEM (3 * TNSTAGE)  // 101376
__global__ __launch_bounds__(256, 2) void gemm_fuse_tn(
        const bf16* __restrict__ Acat, const bf16* __restrict__ B,
        const float* __restrict__ bias, float* __restrict__ C) {
    extern __shared__ uint8_t smem[];
    const uint32_t sbase = smem_u32(smem);
    const int tid = threadIdx.x;
    const int lane = tid & 31, warp = tid >> 5;
    const int wm = warp >> 2, wn = warp & 3;
    const int g = lane >> 2, q = lane & 3;
    const int K = 768, N = 256;
    const size_t m0 = (size_t)blockIdx.y * 128;
    const int n0 = blockIdx.x * 128;
    const int bglob = (int)(m0 >> 14);
    const int p0 = (int)(m0 & 16383);
    const bf16* Ag = Acat + ((size_t)bglob * 768) * NHW + p0;
    const bf16* Bg = B + (size_t)n0 * K;
    const int ntiles = 12;

    float acc[4][4][4];
    #pragma unroll
    for (int i = 0; i < 4; i++)
        #pragma unroll
        for (int j = 0; j < 4; j++)
            #pragma unroll
            for (int k = 0; k < 4; k++) acc[i][j][k] = 0.0f;

    auto load_stage = [&](int st, int k0) {
        uint32_t sa = sbase + st * TNSTAGE;
        uint32_t sb = sa + 64 * 272;
        #pragma unroll
        for (int i = 0; i < 4; i++) {
            int id = i * 256 + tid;
            int arow = id >> 4, ach = id & 15;
            cp_async16(sa + arow * 272 + ach * 16,
                       Ag + (size_t)(k0 + arow) * NHW + ach * 8);
            int brow = id >> 3, bgrp = id & 7;
            cp_async16(sb + brow * 128 + ((bgrp ^ (brow & 7)) << 4),
                       Bg + (size_t)brow * K + k0 + bgrp * 8);
        }
    };

    load_stage(0, 0);  cp_commit();
    load_stage(1, 64); cp_commit();
    cp_wait<1>();
    __syncthreads();

    const int atile = lane >> 3;
    const int arr   = lane & 7;
    const int ak_half = (atile >> 1) << 3;
    const int am_half = (atile & 1) << 3;

    for (int kt = 0; kt < ntiles; kt++) {
        if (kt + 2 < ntiles) load_stage((kt + 2) % 3, (kt + 2) << 6);
        cp_commit();

        uint32_t sa = sbase + (kt % 3) * TNSTAGE;
        uint32_t sb = sa + 64 * 272;
        #pragma unroll
        for (int kc = 0; kc < 4; kc++) {
            uint32_t afr[4][4], bfr[4][2];
            int klocal = kc * 16 + ak_half + arr;
            #pragma unroll
            for (int mt = 0; mt < 4; mt++) {
                int moff = wm * 64 + mt * 16 + am_half;
                uint32_t addr = sa + klocal * 272 + moff * 2;
                ldsm_x4_t(afr[mt][0], afr[mt][1], afr[mt][2], afr[mt][3], addr);
            }
            int rsel = lane & 15;
            int gsel = kc * 2 + (lane >> 4);
            #pragma unroll
            for (int h = 0; h < 2; h++) {
                int row = wn * 32 + h * 16 + rsel;
                uint32_t addr = sb + row * 128 + ((gsel ^ (row & 7)) << 4);
                uint32_t x, y, z, w;
                ldsm_x4(x, y, z, w, addr);
                bfr[2 * h][0] = x;     bfr[2 * h][1] = z;
                bfr[2 * h + 1][0] = y; bfr[2 * h + 1][1] = w;
            }
            #pragma unroll
            for (int mt = 0; mt < 4; mt++)
                #pragma unroll
                for (int nt = 0; nt < 4; nt++)
                    mma_bf16(acc[mt][nt], afr[mt], bfr[nt]);
        }
        cp_wait<1>();
        __syncthreads();
    }

    #pragma unroll
    for (int mt = 0; mt < 4; mt++) {
        size_t rg = m0 + wm * 64 + mt * 16 + g;
        #pragma unroll
        for (int nt = 0; nt < 4; nt++) {
            int cb = n0 + wn * 32 + nt * 8 + 2 * q;
            float b0 = bias[cb], b1 = bias[cb + 1];
            *(float2*)&C[rg * N + cb] =
                make_float2(acc[mt][nt][0] + b0, acc[mt][nt][1] + b1);
            *(float2*)&C[(rg + 8) * N + cb] =
                make_float2(acc[mt][nt][2] + b0, acc[mt][nt][3] + b1);
        }
    }
}

// ================= tensor-core attention, L=64, D=32 (mma.sync) =================
__global__ void attn_kernel(const bf16* __restrict__ QKV, bf16* __restrict__ O) {
    __shared__ uint32_t sq[64 * 24];
    __shared__ uint32_t sk[64 * 24];
    __shared__ uint32_t sv[32 * 40];
    int wh = blockIdx.x;
    int win = wh >> 3, head = wh & 7;
    int tid = threadIdx.x;
    int warp = tid >> 5, lane = tid & 31;
    int g = lane >> 2, q = lane & 3;
    const bf16* base = QKV + (size_t)win * 64 * 768 + head * 32;

    {
        int r = tid >> 1, ch = tid & 1;
        int sw = ch ^ ((r >> 2) & 1);
        const bf16* src = base + (size_t)r * 768 + ch * 16;
        uint4 lo = *(const uint4*)src;
        uint4 hi = *(const uint4*)(src + 8);
        uint2* dst = (uint2*)(sq + r * 24 + sw * 8);
        dst[0] = make_uint2(lo.x, hi.x); dst[1] = make_uint2(lo.y, hi.y);
        dst[2] = make_uint2(lo.z, hi.z); dst[3] = make_uint2(lo.w, hi.w);
        lo = *(const uint4*)(src + 256);
        hi = *(const uint4*)(src + 264);
        dst = (uint2*)(sk + r * 24 + sw * 8);
        dst[0] = make_uint2(lo.x, hi.x); dst[1] = make_uint2(lo.y, hi.y);
        dst[2] = make_uint2(lo.z, hi.z); dst[3] = make_uint2(lo.w, hi.w);
    }
    {
        int jp = tid >> 2, d0 = (tid & 3) * 8;
        int j = jp * 2;
        const bf16* v0p = base + (size_t)j * 768 + 512 + d0;
        uint4 v0 = *(const uint4*)v0p;
        uint4 v1 = *(const uint4*)(v0p + 768);
        uint32_t u0[4] = {v0.x, v0.y, v0.z, v0.w};
        uint32_t u1[4] = {v1.x, v1.y, v1.z, v1.w};
        int cj = jp >> 3;
        int pr = jp & 7;
        int wp = ((pr & 3) << 1) | (pr >> 2);
        #pragma unroll
        for (int m = 0; m < 4; m++) {
            int d = d0 + 2 * m;
            uint32_t loP = (u0[m] & 0xffffu) | (u1[m] << 16);
            uint32_t hiP = (u0[m] >> 16) | (u1[m] & 0xffff0000u);
            sv[d * 40 + ((cj ^ ((d >> 2) & 3)) * 8) + wp] = loP;
            sv[(d + 1) * 40 + ((cj ^ (((d + 1) >> 2) & 3)) * 8) + wp] = hiP;
        }
    }
    __syncthreads();

    float sacc[8][4];
    #pragma unroll
    for (int nt = 0; nt < 8; nt++)
        #pragma unroll
        for (int i = 0; i < 4; i++) sacc[nt][i] = 0.0f;
    #pragma unroll
    for (int kc = 0; kc < 2; kc++) {
        int r0 = warp * 16 + g, r1 = r0 + 8;
        uint2 lo = *(uint2*)&sq[r0 * 24 + ((kc ^ ((r0 >> 2) & 1)) * 8) + 2 * q];
        uint2 hi = *(uint2*)&sq[r1 * 24 + ((kc ^ ((r1 >> 2) & 1)) * 8) + 2 * q];
        uint32_t a[4] = {lo.x, hi.x, lo.y, hi.y};
        #pragma unroll
        for (int nt = 0; nt < 8; nt++) {
            int rn = nt * 8 + g;
            uint2 bb = *(uint2*)&sk[rn * 24 + ((kc ^ ((rn >> 2) & 1)) * 8) + 2 * q];
            uint32_t bfv[2] = {bb.x, bb.y};
            mma_bf16(sacc[nt], a, bfv);
        }
    }

    const float scale = 0.17677669529663687f;
    #pragma unroll
    for (int nt = 0; nt < 8; nt++)
        #pragma unroll
        for (int i = 0; i < 4; i++) sacc[nt][i] *= scale;
    float mx0 = -1e30f, mx1 = -1e30f;
    #pragma unroll
    for (int nt = 0; nt < 8; nt++) {
        mx0 = fmaxf(mx0, fmaxf(sacc[nt][0], sacc[nt][1]));
        mx1 = fmaxf(mx1, fmaxf(sacc[nt][2], sacc[nt][3]));
    }
    mx0 = fmaxf(mx0, __shfl_xor_sync(0xffffffff, mx0, 1));
    mx0 = fmaxf(mx0, __shfl_xor_sync(0xffffffff, mx0, 2));
    mx1 = fmaxf(mx1, __shfl_xor_sync(0xffffffff, mx1, 1));
    mx1 = fmaxf(mx1, __shfl_xor_sync(0xffffffff, mx1, 2));
    float sum0 = 0.0f, sum1 = 0.0f;
    #pragma unroll
    for (int nt = 0; nt < 8; nt++) {
        sacc[nt][0] = __expf(sacc[nt][0] - mx0);
        sacc[nt][1] = __expf(sacc[nt][1] - mx0);
        sacc[nt][2] = __expf(sacc[nt][2] - mx1);
        sacc[nt][3] = __expf(sacc[nt][3] - mx1);
        sum0 += sacc[nt][0] + sacc[nt][1];
        sum1 += sacc[nt][2] + sacc[nt][3];
    }
    sum0 += __shfl_xor_sync(0xffffffff, sum0, 1);
    sum0 += __shfl_xor_sync(0xffffffff, sum0, 2);
    sum1 += __shfl_xor_sync(0xffffffff, sum1, 1);
    sum1 += __shfl_xor_sync(0xffffffff, sum1, 2);
    float inv0 = 1.0f / sum0, inv1 = 1.0f / sum1;
    #pragma unroll
    for (int nt = 0; nt < 8; nt++) {
        sacc[nt][0] *= inv0; sacc[nt][1] *= inv0;
        sacc[nt][2] *= inv1; sacc[nt][3] *= inv1;
    }

    float oacc[4][4];
    #pragma unroll
    for (int nt = 0; nt < 4; nt++)
        #pragma unroll
        for (int i = 0; i < 4; i++) oacc[nt][i] = 0.0f;
    #pragma unroll
    for (int kc = 0; kc < 4; kc++) {
        uint32_t a[4];
        a[0] = f2bf2(sacc[2 * kc][0], sacc[2 * kc][1]);
        a[1] = f2bf2(sacc[2 * kc][2], sacc[2 * kc][3]);
        a[2] = f2bf2(sacc[2 * kc + 1][0], sacc[2 * kc + 1][1]);
        a[3] = f2bf2(sacc[2 * kc + 1][2], sacc[2 * kc + 1][3]);
        #pragma unroll
        for (int nt = 0; nt < 4; nt++) {
            int rn = nt * 8 + g;
            uint2 bb = *(uint2*)&sv[rn * 40 + ((kc ^ ((rn >> 2) & 3)) * 8) + 2 * q];
            uint32_t bfv[2] = {bb.x, bb.y};
            mma_bf16(oacc[nt], a, bfv);
        }
    }

    int row0 = win * 64 + warp * 16 + g;
    bf16* o0 = O + (size_t)row0 * NC + head * 32;
    bf16* o1 = o0 + 8 * NC;
    #pragma unroll
    for (int nt = 0; nt < 4; nt++) {
        int cb = nt * 8 + 2 * q;
        *(uint32_t*)&o0[cb] = f2bf2(oacc[nt][0], oacc[nt][1]);
        *(uint32_t*)&o1[cb] = f2bf2(oacc[nt][2], oacc[nt][3]);
    }
}

// ---------------- launch ----------------
extern "C" void kernel_launch(void* const* d_in, const int* in_sizes, int n_in,
                              void* d_out, int out_size) {
    const float* x      = (const float*)d_in[0];
    const float* w1     = (const float*)d_in[1];
    const float* b1     = (const float*)d_in[2];
    const float* w2     = (const float*)d_in[3];
    const float* b2     = (const float*)d_in[4];
    const float* w3     = (const float*)d_in[5];
    const float* b3     = (const float*)d_in[6];
    const float* wf     = (const float*)d_in[7];
    const float* bf     = (const float*)d_in[8];
    const float* gw     = (const float*)d_in[9];
    const float* bw     = (const float*)d_in[10];
    const float* wqkv_w = (const float*)d_in[11];
    const float* bqkv_w = (const float*)d_in[12];
    const float* wo_w   = (const float*)d_in[13];
    const float* bo_w   = (const float*)d_in[14];
    const float* gg     = (const float*)d_in[15];
    const float* bg     = (const float*)d_in[16];
    const float* wqkv_g = (const float*)d_in[17];
    const float* bqkv_g = (const float*)d_in[18];
    const float* wo_g   = (const float*)d_in[19];
    const float* bo_g   = (const float*)d_in[20];
    const float* gm     = (const float*)d_in[21];
    const float* bm     = (const float*)d_in[22];
    const float* m1w    = (const float*)d_in[23];
    const float* m1b    = (const float*)d_in[24];
    const float* m2w    = (const float*)d_in[25];
    const float* m2b    = (const float*)d_in[26];
    float* out = (float*)d_out;

    static bool attrs_set = false;
    if (!attrs_set) {
        cudaFuncSetAttribute(gemm_bf16_nt<float, false>,
                             cudaFuncAttributeMaxDynamicSharedMemorySize, GEMM_SMEM);
        cudaFuncSetAttribute(gemm_bf16_nt<bf16, false>,
                             cudaFuncAttributeMaxDynamicSharedMemorySize, GEMM_SMEM);
        cudaFuncSetAttribute(gemm_bf16_nt<bf16, true>,
                             cudaFuncAttributeMaxDynamicSharedMemorySize, GEMM_SMEM);
        cudaFuncSetAttribute(gemm_fuse_tn,
                             cudaFuncAttributeMaxDynamicSharedMemorySize, TN_SMEM);
        attrs_set = true;
    }

    void *p_cat, *p_xm, *p_xtok, *p_tok, *p_qkv, *p_att, *p_proj, *p_h1, *p_wb;
    cudaGetSymbolAddress(&p_cat, g_cat);
    cudaGetSymbolAddress(&p_xm, g_xm);
    cudaGetSymbolAddress(&p_xtok, g_xtok);
    cudaGetSymbolAddress(&p_tok, g_tok);
    cudaGetSymbolAddress(&p_qkv, g_qkv);
    cudaGetSymbolAddress(&p_att, g_att);
    cudaGetSymbolAddress(&p_proj, g_proj);
    cudaGetSymbolAddress(&p_h1, g_h1);
    cudaGetSymbolAddress(&p_wb, g_wb);
    bf16* cat  = (bf16*)p_cat;
    float* xm  = (float*)p_xm;    float* xtok = (float*)p_xtok;
    bf16* tok  = (bf16*)p_tok;    bf16* qkv  = (bf16*)p_qkv;
    bf16* att  = (bf16*)p_att;    bf16* proj = (bf16*)p_proj;
    bf16* h1   = (bf16*)p_h1;     bf16* wb   = (bf16*)p_wb;

    // all weight conversions in one launch
    cvt_all<<<1216, 256>>>(wf, wqkv_w, wqkv_g, wo_w, wo_g, m1w, m2w, wb);

    // depthwise convs -> cat (bf16, k-major); x -> token-major fp32
    dwconv3_kernel<<<dim3(16, NC, NB), 256>>>(x, w1, b1, w2, b2, w3, b3);
    to_tok<<<dim3(256, 4, NB), 256>>>(x, xtok);

    // 1x1 fuse as TN GEMM (A read k-major) -> xm (fp32)
    gemm_fuse_tn<<<dim3(2, 1024), 256, TN_SMEM>>>(cat, wb + OFF_WF, bf, xm);

    // ---- window branch ----
    ln_perm<<<16384, 256>>>(xm, gw, bw, tok, 0);
    gemm_bf16_nt<bf16, false><<<NPERSIST, 256, GEMM_SMEM>>>(tok, wb + OFF_QKVW, bqkv_w, qkv, 768, 256, 6144);
    attn_kernel<<<16384, 128>>>(qkv, att);
    gemm_bf16_nt<bf16, false><<<NPERSIST, 256, GEMM_SMEM>>>(att, wb + OFF_WOW, bo_w, proj, 256, 256, 2048);
    resadd_ln<<<16384, 256>>>(xtok, proj, xm, gg, bg, tok, 0, 1);

    // ---- grid branch ----
    gemm_bf16_nt<bf16, false><<<NPERSIST, 256, GEMM_SMEM>>>(tok, wb + OFF_QKVG, bqkv_g, qkv, 768, 256, 6144);
    attn_kernel<<<16384, 128>>>(qkv, att);
    gemm_bf16_nt<bf16, false><<<NPERSIST, 256, GEMM_SMEM>>>(att, wb + OFF_WOG, bo_g, proj, 256, 256, 2048);
    resadd_ln<<<16384, 256>>>(xm, proj, xm, gm, bm, tok, 1, 2);

    // ---- MLP ----
    gemm_bf16_nt<bf16, true ><<<NPERSIST, 256, GEMM_SMEM>>>(tok, wb + OFF_M1, m1b, h1, 1024, 256, 8192);
    gemm_bf16_nt<bf16, false><<<NPERSIST, 256, GEMM_SMEM>>>(h1, wb + OFF_M2, m2b, proj, 256, 1024, 2048);
    from_tok_add<<<dim3(256, 4, NB), 256>>>(xm, proj, out);
}